// round 4
// baseline (speedup 1.0000x reference)
#include <cuda_runtime.h>
#include <math.h>

// Problem constants (fixed by setup_inputs): B=2, S=2048, C=64, F=64, K=3
#define Bn   2
#define Sn   2048
#define Cn   64
#define Fn   64
#define Kt   3
#define TS   32               // s-rows per block
#define RMAX 48               // max D-window rows held in smem
#define Mtot (Bn * Sn)        // 4096

// ---- packed f32x2 helpers (Blackwell 2x fp32 FMA path) ----
__device__ __forceinline__ unsigned long long pack2(float lo, float hi) {
    unsigned long long r;
    asm("mov.b64 %0, {%1,%2};" : "=l"(r) : "f"(lo), "f"(hi));
    return r;
}
__device__ __forceinline__ void fma2(unsigned long long& d,
                                     unsigned long long a, unsigned long long b) {
    asm("fma.rn.f32x2 %0, %1, %2, %0;" : "+l"(d) : "l"(a), "l"(b));
}
__device__ __forceinline__ float2 unpack2(unsigned long long v) {
    float2 f;
    asm("mov.b64 {%0,%1}, %2;" : "=f"(f.x), "=f"(f.y) : "l"(v));
    return f;
}

// Fused kernel: per block, compute the D window (GEMM) in smem, then gather+lerp.
// smem buffer is reused: phase A holds xs[64][50] + ws[32][192]; phase B holds D[48][192].
__global__ __launch_bounds__(256) void ddc_fused(
    const float* __restrict__ x,   // (B,S,C)
    const float* __restrict__ kw,  // (F,C,K)
    const float* __restrict__ ow,  // (F,)
    const void*  __restrict__ dilp,
    float*       __restrict__ out) // (B,S,F)
{
    __shared__ __align__(16) float sbuf[Cn * 50 + 32 * 192];  // 9344 floats = 37.4KB
    __shared__ float s_w[Fn];
    __shared__ int   s_I[Fn];
    __shared__ int   s_lo, s_flag, s_dil;

    const int tid = threadIdx.x;
    const int rq0 = blockIdx.x * TS;     // global row base (b*S + s0)
    const int b   = rq0 >> 11;           // S = 2048
    const int s0  = rq0 & (Sn - 1);

    // --- offsets: I_f = floor(off_f), w_f = frac(off_f) ---
    if (tid < Fn) {
        int d = *(const int*)dilp;                        // int32/int64 little-endian
        if (d < 1 || d > 65536) d = (int)(*(const float*)dilp);  // float scalar case
        if (tid == 0) s_dil = d;
        float mo  = 0.5f * (float)Sn / (float)(d * Kt);
        float o   = ow[tid];
        float off = -mo / (1.0f + expf(-o));              // -sigmoid(o)*max_offset
        float fl  = floorf(off);
        s_I[tid] = (int)fl;
        s_w[tid] = off - fl;
    }
    __syncthreads();
    if (tid == 0) {
        int Imin = s_I[0], Imax = s_I[0];
        #pragma unroll
        for (int f = 1; f < Fn; f++) { int v = s_I[f]; Imin = min(Imin, v); Imax = max(Imax, v); }
        int d  = s_dil;
        int lo = s0 + Imin - (Kt - 1) * d; if (lo < 0) lo = 0;
        int hi = s0 + TS - 1 + Imax + 1;   if (hi > Sn - 1) hi = Sn - 1;
        s_lo   = lo;
        s_flag = (hi - lo + 1 > RMAX) ? 1 : 0;
    }
    __syncthreads();

    const int lo   = s_lo;
    const int flag = s_flag;
    const int dil  = s_dil;
    const int f    = tid & 63;
    const int sl   = tid >> 6;
    const float w  = s_w[f];
    const int   I  = s_I[f];

    if (!flag) {
        float* xs = sbuf;             // xs[c*50 + r], r in [0,RMAX)
        float* ws = sbuf + Cn * 50;   // ws[c_rel*192 + k*64 + f]

        // Stage x window, transposed (coalesced 128B reads; clamped rows for padding).
        #pragma unroll
        for (int it = 0; it < (RMAX * Cn) / 256; it++) {
            int idx = tid + it * 256;
            int r = idx >> 6, c = idx & 63;
            int gr = lo + r; if (gr > Sn - 1) gr = Sn - 1;
            xs[c * 50 + r] = x[(b * Sn + gr) * Cn + c];
        }

        const int tx = tid & 31;      // col lane: n = tx + 32j
        const int ty = tid >> 5;      // warp: row pairs p = ty + 8i

        unsigned long long acc[3][6];
        #pragma unroll
        for (int i = 0; i < 3; i++)
            #pragma unroll
            for (int j = 0; j < 6; j++) acc[i][j] = 0ull;

        const float4* kw4 = (const float4*)kw;
        for (int h = 0; h < 2; h++) {             // two 32-channel phases
            __syncthreads();                      // xs ready / prior ws reads done
            // Stage this phase's weights transposed: float4-coalesced global reads.
            #pragma unroll
            for (int it = 0; it < 6; it++) {
                int q = tid + it * 256;           // q < 1536
                int ff = q / 24;
                int m  = q - ff * 24;
                float4 v = kw4[ff * 48 + h * 24 + m];
                int t = 4 * m;
                { int c = (t    ) / 3, k = (t    ) - 3 * c; ws[c * 192 + k * 64 + ff] = v.x; }
                { int c = (t + 1) / 3, k = (t + 1) - 3 * c; ws[c * 192 + k * 64 + ff] = v.y; }
                { int c = (t + 2) / 3, k = (t + 2) - 3 * c; ws[c * 192 + k * 64 + ff] = v.z; }
                { int c = (t + 3) / 3, k = (t + 3) - 3 * c; ws[c * 192 + k * 64 + ff] = v.w; }
            }
            __syncthreads();

            const float* xsp = xs + h * 32 * 50;  // absolute c = h*32 + cr
            #pragma unroll 8
            for (int cr = 0; cr < 32; cr++) {
                unsigned long long xv[3];
                #pragma unroll
                for (int i = 0; i < 3; i++) {
                    float2 p = *(const float2*)(xsp + cr * 50 + 2 * (ty + 8 * i));  // LDS.64 bcast
                    xv[i] = pack2(p.x, p.y);
                }
                #pragma unroll
                for (int j = 0; j < 6; j++) {
                    float wsc = ws[cr * 192 + tx + 32 * j];   // conflict-free
                    unsigned long long wv = pack2(wsc, wsc);
                    #pragma unroll
                    for (int i = 0; i < 3; i++) fma2(acc[i][j], xv[i], wv);
                }
            }
        }
        __syncthreads();

        // Dump D tile into the (now free) staging buffer: D[r*192 + n].
        float* D = sbuf;
        #pragma unroll
        for (int i = 0; i < 3; i++) {
            int p = ty + 8 * i;
            #pragma unroll
            for (int j = 0; j < 6; j++) {
                float2 v = unpack2(acc[i][j]);
                D[(2 * p)     * 192 + tx + 32 * j] = v.x;
                D[(2 * p + 1) * 192 + tx + 32 * j] = v.y;
            }
        }
        __syncthreads();

        // Gather + lerp from smem; coalesced store.
        #pragma unroll
        for (int jj = 0; jj < 8; jj++) {
            int s = s0 + sl * 8 + jj;
            float y = 0.0f;
            #pragma unroll
            for (int k = 0; k < Kt; k++) {
                int i0  = s - k * dil + I;
                int i0c = min(max(i0,     0), Sn - 1);
                int i1c = min(max(i0 + 1, 0), Sn - 1);
                float d0 = D[(i0c - lo) * 192 + k * 64 + f];
                float d1 = D[(i1c - lo) * 192 + k * 64 + f];
                y += d0 + w * (d1 - d0);
            }
            out[(rq0 + sl * 8 + jj) * Fn + f] = y;
        }
    } else {
        // Correct fallback for pathological offset spread (never triggers with this data):
        // naive per-output dot from global memory.
        for (int jj = 0; jj < 8; jj++) {
            int s = s0 + sl * 8 + jj;
            float y = 0.0f;
            for (int k = 0; k < Kt; k++) {
                int i0  = s - k * dil + I;
                int i0c = min(max(i0,     0), Sn - 1);
                int i1c = min(max(i0 + 1, 0), Sn - 1);
                float a0 = 0.0f, a1 = 0.0f;
                for (int c = 0; c < Cn; c++) {
                    float kk = kw[f * (Cn * Kt) + c * Kt + k];
                    a0 += x[(b * Sn + i0c) * Cn + c] * kk;
                    a1 += x[(b * Sn + i1c) * Cn + c] * kk;
                }
                y += a0 + w * (a1 - a0);
            }
            out[(rq0 + sl * 8 + jj) * Fn + f] = y;
        }
    }
}

extern "C" void kernel_launch(void* const* d_in, const int* in_sizes, int n_in,
                              void* d_out, int out_size)
{
    const float* x   = (const float*)d_in[0];   // (B,S,C) f32
    const float* kw  = (const float*)d_in[1];   // (F,C,K) f32
    const float* ow  = (const float*)d_in[2];   // (F,)    f32
    const void*  dil = d_in[3];                 // scalar dilation_rate

    ddc_fused<<<Mtot / TS, 256>>>(x, kw, ow, dil, (float*)d_out);
}